// round 2
// baseline (speedup 1.0000x reference)
#include <cuda_runtime.h>
#include <math.h>

#define NN 8000
#define EE 24000
#define EAA 32000
#define BB 256
#define ATOMD 133
#define BONDD 14
#define HD 256
#define NHEADS 8
#define HHD 2048
#define NLAYERS 5

// ---------------- scratch (device globals; no allocation allowed) -------------
__device__ float g_h[NN * HD];            // node features
__device__ float g_out[NN * HD];          // message accumulator
__device__ float g_xl[NN * HHD];          // h @ Wl
__device__ float g_xr[NN * HHD];          // h @ Wr
__device__ float g_score[EAA * NHEADS];   // scores, then exp(score - m)
__device__ unsigned g_m[NN * NHEADS];     // segment max (encoded)
__device__ float g_s[NN * NHEADS];        // segment sum of exp
__device__ float g_deg[NN];
__device__ float g_loopsum[NN * BONDD];
__device__ float g_loop[NN * BONDD];      // self-loop edge attr (mean of incoming)
__device__ float g_gate[NN];
__device__ float g_ge[NN];
__device__ unsigned g_gm[BB];
__device__ float g_gs[BB];

// monotonic float<->uint map for atomicMax on floats
__device__ __forceinline__ unsigned fenc(float f) {
    unsigned u = __float_as_uint(f);
    return (u & 0x80000000u) ? ~u : (u | 0x80000000u);
}
__device__ __forceinline__ float fdec(unsigned u) {
    u = (u & 0x80000000u) ? (u & 0x7FFFFFFFu) : ~u;
    return __uint_as_float(u);
}
#define ENC_NEG_INF 0x007FFFFFu  // fenc(-inf)

// ---------------- pre: self-loop attr = mean of incoming edge_attr ------------
__global__ void k_init_pre() {
    int i = blockIdx.x * blockDim.x + threadIdx.x;
    if (i < NN * BONDD) g_loopsum[i] = 0.f;
    if (i < NN) g_deg[i] = 0.f;
}

__global__ void k_degattr(const int* __restrict__ dst, const float* __restrict__ ea) {
    int j = blockIdx.x * blockDim.x + threadIdx.x;
    if (j >= EE * BONDD) return;
    int e = j / BONDD, b = j - e * BONDD;
    int d = dst[e];
    atomicAdd(&g_loopsum[d * BONDD + b], ea[j]);
    if (b == 0) atomicAdd(&g_deg[d], 1.f);
}

__global__ void k_loopdiv() {
    int j = blockIdx.x * blockDim.x + threadIdx.x;
    if (j >= NN * BONDD) return;
    int n = j / BONDD;
    g_loop[j] = g_loopsum[j] / fmaxf(g_deg[n], 1.f);
}

// ---------------- atom embedding: relu(LN(x @ W + b)) ------------------------
__global__ void k_embed(const float* __restrict__ x, const float* __restrict__ W,
                        const float* __restrict__ b, const float* __restrict__ g,
                        const float* __restrict__ be) {
    int n = blockIdx.x, tid = threadIdx.x;  // 256 threads
    __shared__ float sx[ATOMD];
    __shared__ float rs[8], rq[8];
    if (tid < ATOMD) sx[tid] = x[n * ATOMD + tid];
    __syncthreads();
    float acc = b[tid];
    for (int k = 0; k < ATOMD; k++) acc += sx[k] * W[k * HD + tid];
    float a = acc, q = acc * acc;
    #pragma unroll
    for (int o = 16; o; o >>= 1) {
        a += __shfl_xor_sync(~0u, a, o);
        q += __shfl_xor_sync(~0u, q, o);
    }
    int lane = tid & 31, w = tid >> 5;
    if (!lane) { rs[w] = a; rq[w] = q; }
    __syncthreads();
    float sum = 0.f, sq = 0.f;
    #pragma unroll
    for (int i = 0; i < 8; i++) { sum += rs[i]; sq += rq[i]; }
    float mean = sum * (1.f / HD);
    float var = sq * (1.f / HD) - mean * mean;
    float y = (acc - mean) * rsqrtf(var + 1e-5f) * g[tid] + be[tid];
    g_h[n * HD + tid] = fmaxf(y, 0.f);
}

// ---------------- SGEMM: C[which] = g_h[8000,256] @ Wm[256,2048] --------------
// 128x128x8 register-blocked, 256 threads, 8x8 per thread.
__global__ void k_sgemm(const float* __restrict__ Wm, int which) {
    __shared__ float As[8][128];
    __shared__ float Bs[8][128];
    float* C = which ? g_xr : g_xl;
    int t = threadIdx.x;
    int m0 = blockIdx.y * 128;
    int n0 = blockIdx.x * 128;
    int ty = t / 16, tx = t % 16;
    float acc[8][8] = {};
    int arow = t >> 1;            // 0..127
    int acol = (t & 1) * 4;       // 0 or 4
    int brow = t >> 5;            // 0..7
    int bcol = (t & 31) * 4;      // 0..124

    for (int k0 = 0; k0 < HD; k0 += 8) {
        float4 av = make_float4(0.f, 0.f, 0.f, 0.f);
        if (m0 + arow < NN)
            av = *(const float4*)&g_h[(m0 + arow) * HD + k0 + acol];
        As[acol + 0][arow] = av.x;
        As[acol + 1][arow] = av.y;
        As[acol + 2][arow] = av.z;
        As[acol + 3][arow] = av.w;
        *(float4*)&Bs[brow][bcol] = *(const float4*)&Wm[(k0 + brow) * HHD + n0 + bcol];
        __syncthreads();
        #pragma unroll
        for (int k = 0; k < 8; k++) {
            float a[8], b[8];
            *(float4*)&a[0] = *(float4*)&As[k][ty * 8];
            *(float4*)&a[4] = *(float4*)&As[k][ty * 8 + 4];
            *(float4*)&b[0] = *(float4*)&Bs[k][tx * 8];
            *(float4*)&b[4] = *(float4*)&Bs[k][tx * 8 + 4];
            #pragma unroll
            for (int i = 0; i < 8; i++)
                #pragma unroll
                for (int j = 0; j < 8; j++)
                    acc[i][j] += a[i] * b[j];
        }
        __syncthreads();
    }
    #pragma unroll
    for (int i = 0; i < 8; i++) {
        int m = m0 + ty * 8 + i;
        if (m < NN) {
            #pragma unroll
            for (int j = 0; j < 8; j += 4)
                *(float4*)&C[m * HHD + n0 + tx * 8 + j] =
                    make_float4(acc[i][j], acc[i][j + 1], acc[i][j + 2], acc[i][j + 3]);
        }
    }
}

// ---------------- per-layer zero/init -----------------------------------------
__global__ void k_init_layer() {
    int i = blockIdx.x * blockDim.x + threadIdx.x;
    if (i < NN * HD) g_out[i] = 0.f;
    if (i < NN * NHEADS) { g_s[i] = 0.f; g_m[i] = ENC_NEG_INF; }
}

// ---------------- edge score: leaky(xl[s]+xr[d]+ea@We) . att  -----------------
// one block per (augmented) edge, 256 threads (one per feature dim)
__global__ void k_score(const int* __restrict__ src, const int* __restrict__ dst,
                        const float* __restrict__ edge_attr,
                        const float* __restrict__ We_l, const float* __restrict__ att_l) {
    int e = blockIdx.x, tid = threadIdx.x;
    __shared__ float sea[BONDD];
    __shared__ float wsum[NHEADS * 8];
    int s, d;
    const float* ea;
    if (e < EE) { s = src[e]; d = dst[e]; ea = edge_attr + e * BONDD; }
    else        { s = d = e - EE;          ea = g_loop + (e - EE) * BONDD; }
    if (tid < BONDD) sea[tid] = ea[tid];
    __syncthreads();
    const float* xlrow = g_xl + s * HHD;
    const float* xrrow = g_xr + d * HHD;
    float part[NHEADS];
    #pragma unroll
    for (int h = 0; h < NHEADS; h++) {
        int c = h * HD + tid;
        float eev = 0.f;
        #pragma unroll
        for (int b = 0; b < BONDD; b++) eev += sea[b] * We_l[b * HHD + c];
        float v = xlrow[c] + xrrow[c] + eev;
        v = v > 0.f ? v : 0.2f * v;
        part[h] = v * att_l[c];
    }
    int lane = tid & 31, w = tid >> 5;
    #pragma unroll
    for (int h = 0; h < NHEADS; h++) {
        float v = part[h];
        #pragma unroll
        for (int o = 16; o; o >>= 1) v += __shfl_xor_sync(~0u, v, o);
        if (!lane) wsum[h * 8 + w] = v;
    }
    __syncthreads();
    if (tid < NHEADS) {
        float v = 0.f;
        #pragma unroll
        for (int w2 = 0; w2 < 8; w2++) v += wsum[tid * 8 + w2];
        g_score[e * NHEADS + tid] = v;
        atomicMax(&g_m[d * NHEADS + tid], fenc(v));
    }
}

// ---------------- exp(score - max) + segment sum ------------------------------
__global__ void k_expsum(const int* __restrict__ dst) {
    int j = blockIdx.x * blockDim.x + threadIdx.x;
    if (j >= EAA * NHEADS) return;
    int e = j / NHEADS, h = j - e * NHEADS;
    int d = (e < EE) ? dst[e] : (e - EE);
    float ex = expf(g_score[j] - fdec(g_m[d * NHEADS + h]));
    g_score[j] = ex;
    atomicAdd(&g_s[d * NHEADS + h], ex);
}

// ---------------- message: out[d] += mean_h( xl[s,h,:] * alpha[e,h] ) ---------
__global__ void k_message(const int* __restrict__ src, const int* __restrict__ dst) {
    int e = blockIdx.x, tid = threadIdx.x;
    __shared__ float alpha[NHEADS];
    int s, d;
    if (e < EE) { s = src[e]; d = dst[e]; }
    else        { s = d = e - EE; }
    if (tid < NHEADS)
        alpha[tid] = g_score[e * NHEADS + tid] / g_s[d * NHEADS + tid];
    __syncthreads();
    const float* xlrow = g_xl + s * HHD;
    float acc = 0.f;
    #pragma unroll
    for (int h = 0; h < NHEADS; h++) acc += xlrow[h * HD + tid] * alpha[h];
    atomicAdd(&g_out[d * HD + tid], 0.125f * acc);
}

// ---------------- residual + LayerNorm ----------------------------------------
__global__ void k_resln(const float* __restrict__ bias_l, const float* __restrict__ g,
                        const float* __restrict__ be) {
    int n = blockIdx.x, tid = threadIdx.x;
    __shared__ float rs[8], rq[8];
    float v = g_out[n * HD + tid] + bias_l[tid] + g_h[n * HD + tid];
    float a = v, q = v * v;
    #pragma unroll
    for (int o = 16; o; o >>= 1) {
        a += __shfl_xor_sync(~0u, a, o);
        q += __shfl_xor_sync(~0u, q, o);
    }
    int lane = tid & 31, w = tid >> 5;
    if (!lane) { rs[w] = a; rq[w] = q; }
    __syncthreads();
    float sum = 0.f, sq = 0.f;
    #pragma unroll
    for (int i = 0; i < 8; i++) { sum += rs[i]; sq += rq[i]; }
    float mean = sum * (1.f / HD);
    float var = sq * (1.f / HD) - mean * mean;
    g_h[n * HD + tid] = (v - mean) * rsqrtf(var + 1e-5f) * g[tid] + be[tid];
}

// ---------------- readout -----------------------------------------------------
__global__ void k_initread(float* __restrict__ out) {
    int i = blockIdx.x * blockDim.x + threadIdx.x;
    if (i < BB * HD) out[i] = 0.f;
    if (i < BB) { g_gm[i] = ENC_NEG_INF; g_gs[i] = 0.f; }
}

__global__ void k_gate(const float* __restrict__ W1, const float* __restrict__ b1,
                       const float* __restrict__ W2, const float* __restrict__ b2,
                       const int* __restrict__ batch) {
    int n = blockIdx.x, tid = threadIdx.x;  // 128 threads
    __shared__ float sh[HD];
    __shared__ float rs[4];
    sh[tid] = g_h[n * HD + tid];
    sh[tid + 128] = g_h[n * HD + tid + 128];
    __syncthreads();
    float acc = b1[tid];
    for (int k = 0; k < HD; k++) acc += sh[k] * W1[k * 128 + tid];
    float part = fmaxf(acc, 0.f) * W2[tid];
    #pragma unroll
    for (int o = 16; o; o >>= 1) part += __shfl_xor_sync(~0u, part, o);
    int lane = tid & 31, w = tid >> 5;
    if (!lane) rs[w] = part;
    __syncthreads();
    if (tid == 0) {
        float gate = rs[0] + rs[1] + rs[2] + rs[3] + b2[0];
        g_gate[n] = gate;
        atomicMax(&g_gm[batch[n]], fenc(gate));
    }
}

__global__ void k_gexp(const int* __restrict__ batch) {
    int n = blockIdx.x * blockDim.x + threadIdx.x;
    if (n >= NN) return;
    int b = batch[n];
    float ge = expf(g_gate[n] - fdec(g_gm[b]));
    g_ge[n] = ge;
    atomicAdd(&g_gs[b], ge);
}

__global__ void k_readout(const int* __restrict__ batch, float* __restrict__ out) {
    int n = blockIdx.x, tid = threadIdx.x;
    int b = batch[n];
    float w = g_ge[n] / fmaxf(g_gs[b], 1e-16f);
    atomicAdd(&out[b * HD + tid], w * g_h[n * HD + tid]);
}

// ---------------- launcher ----------------------------------------------------
extern "C" void kernel_launch(void* const* d_in, const int* in_sizes, int n_in,
                              void* d_out, int out_size) {
    const float* x         = (const float*)d_in[0];
    const float* edge_attr = (const float*)d_in[1];
    const float* emb_W     = (const float*)d_in[2];
    const float* emb_b     = (const float*)d_in[3];
    const float* emb_g     = (const float*)d_in[4];
    const float* emb_beta  = (const float*)d_in[5];
    const float* Wl        = (const float*)d_in[6];
    const float* Wr        = (const float*)d_in[7];
    const float* We        = (const float*)d_in[8];
    const float* att       = (const float*)d_in[9];
    const float* bias      = (const float*)d_in[10];
    const float* ln_g      = (const float*)d_in[11];
    const float* ln_b      = (const float*)d_in[12];
    const float* g1W       = (const float*)d_in[13];
    const float* g1b       = (const float*)d_in[14];
    const float* g2W       = (const float*)d_in[15];
    const float* g2b       = (const float*)d_in[16];
    const int* edge_index  = (const int*)d_in[17];
    const int* batch       = (const int*)d_in[18];
    const int* src = edge_index;
    const int* dst = edge_index + EE;
    float* out = (float*)d_out;

    k_init_pre<<<(NN * BONDD + 255) / 256, 256>>>();
    k_degattr<<<(EE * BONDD + 255) / 256, 256>>>(dst, edge_attr);
    k_loopdiv<<<(NN * BONDD + 255) / 256, 256>>>();
    k_embed<<<NN, HD>>>(x, emb_W, emb_b, emb_g, emb_beta);

    dim3 gg(HHD / 128, (NN + 127) / 128);
    for (int l = 0; l < NLAYERS; l++) {
        k_init_layer<<<(NN * HD + 255) / 256, 256>>>();
        k_sgemm<<<gg, 256>>>(Wl + (size_t)l * HD * HHD, 0);
        k_sgemm<<<gg, 256>>>(Wr + (size_t)l * HD * HHD, 1);
        k_score<<<EAA, HD>>>(src, dst, edge_attr,
                             We + (size_t)l * BONDD * HHD,
                             att + (size_t)l * NHEADS * HD);
        k_expsum<<<(EAA * NHEADS + 255) / 256, 256>>>(dst);
        k_message<<<EAA, HD>>>(src, dst);
        k_resln<<<NN, HD>>>(bias + l * HD, ln_g + l * HD, ln_b + l * HD);
    }

    k_initread<<<(BB * HD + 255) / 256, 256>>>(out);
    k_gate<<<NN, 128>>>(g1W, g1b, g2W, g2b, batch);
    k_gexp<<<(NN + 255) / 256, 256>>>(batch);
    k_readout<<<NN, HD>>>(batch, out);
}